// round 1
// baseline (speedup 1.0000x reference)
#include <cuda_runtime.h>
#include <cuda_bf16.h>

#define NN 50000
#define NE 500000
#define NG 512
#define DD 128
#define NO 64
#define NT 11
#define SCAN_BLK 512
#define NCHUNK ((NN + SCAN_BLK - 1) / SCAN_BLK)   // 98

// ---------------- device scratch (no allocations allowed) ----------------
__device__ float g_dinv[NN];
__device__ int   g_degi[NN];
__device__ int   g_rowstart[NN];
__device__ int   g_cursor[NN];
__device__ int   g_csrc[NE];
__device__ float g_cnorm[NE];
__device__ float g_hw[NN * DD];     // h @ W  (message content)
__device__ float g_agg[NN * DD];    // pre-relu layer output
__device__ float g_t11[NT * DD];    // embed @ W0
__device__ float g_pooled[NG * DD];
__device__ float g_counts[NG];
__device__ int   g_chunksum[NCHUNK];
__device__ int   g_chunkoff[NCHUNK];

// ---------------- small helpers ----------------
__device__ __forceinline__ float4 ld4(const float* p) { return *(const float4*)p; }
__device__ __forceinline__ void st4(float* p, float4 v) { *(float4*)p = v; }

// ---------------- degree count ----------------
__global__ void k_deg(const int* __restrict__ dst) {
    int i = blockIdx.x * blockDim.x + threadIdx.x;
    if (i < NE) atomicAdd(&g_degi[dst[i]], 1);
}

__global__ void k_dinv() {
    int i = blockIdx.x * blockDim.x + threadIdx.x;
    if (i < NN) g_dinv[i] = rsqrtf((float)g_degi[i] + 1.0f);
}

// ---------------- prefix scan (3-phase) ----------------
__global__ void k_scan1() {
    __shared__ int sh[SCAN_BLK];
    int c = blockIdx.x;
    int i = c * SCAN_BLK + threadIdx.x;
    int v = (i < NN) ? g_degi[i] : 0;
    sh[threadIdx.x] = v;
    __syncthreads();
    #pragma unroll
    for (int off = 1; off < SCAN_BLK; off <<= 1) {
        int t = (threadIdx.x >= off) ? sh[threadIdx.x - off] : 0;
        __syncthreads();
        sh[threadIdx.x] += t;
        __syncthreads();
    }
    if (i < NN) g_rowstart[i] = sh[threadIdx.x] - v;   // exclusive
    if (threadIdx.x == SCAN_BLK - 1) g_chunksum[c] = sh[SCAN_BLK - 1];
}

__global__ void k_scan2() {
    int run = 0;
    for (int k = 0; k < NCHUNK; k++) {
        int t = g_chunksum[k];
        g_chunkoff[k] = run;
        run += t;
    }
}

__global__ void k_scan3() {
    int i = blockIdx.x * blockDim.x + threadIdx.x;
    if (i < NN) g_rowstart[i] += g_chunkoff[i / SCAN_BLK];
}

// ---------------- CSR fill ----------------
__global__ void k_fill(const int* __restrict__ src, const int* __restrict__ dst) {
    int e = blockIdx.x * blockDim.x + threadIdx.x;
    if (e >= NE) return;
    int s = src[e], d = dst[e];
    int pos = atomicAdd(&g_cursor[d], 1);
    int idx = g_rowstart[d] + pos;
    g_csrc[idx]  = s;
    g_cnorm[idx] = g_dinv[s] * g_dinv[d];
}

// ---------------- t11 = embed @ W0 (11x128) ----------------
__global__ void k_t11(const float* __restrict__ embed, const float* __restrict__ W0) {
    __shared__ float er[DD];
    int r = blockIdx.x;       // 0..10
    int c = threadIdx.x;      // 0..127
    er[c] = embed[r * DD + c];
    __syncthreads();
    float s = 0.f;
    #pragma unroll 8
    for (int k = 0; k < DD; k++) s += er[k] * W0[k * DD + c];
    g_t11[r * DD + c] = s;
}

// ---------------- layer-0: hw = t11[x[n]] ----------------
__global__ void k_init0(const int* __restrict__ x) {
    int idx = blockIdx.x * blockDim.x + threadIdx.x;   // NN*32 threads
    int n = idx >> 5;
    int lane = idx & 31;
    float4 v = ld4(&g_t11[x[n] * DD + lane * 4]);
    st4(&g_hw[n * DD + lane * 4], v);
}

// ---------------- aggregation: agg[n] = b + hw[n]*dinv^2 + sum_e hw[src]*enorm ----------------
__global__ void k_agg(const float* __restrict__ b) {
    int n = blockIdx.x * 8 + (threadIdx.x >> 5);       // warp per node, 6250 blocks x 8 warps
    int lane = threadIdx.x & 31;
    const float4* hw4 = (const float4*)g_hw;

    float sn = g_dinv[n];
    sn = sn * sn;
    float4 bv = ld4(&b[lane * 4]);
    float4 hv = hw4[n * 32 + lane];
    float4 acc;
    acc.x = bv.x + hv.x * sn;
    acc.y = bv.y + hv.y * sn;
    acc.z = bv.z + hv.z * sn;
    acc.w = bv.w + hv.w * sn;

    int beg = g_rowstart[n];
    int cnt = g_degi[n];
    int j = 0;
    for (; j + 4 <= cnt; j += 4) {
        int s0 = g_csrc[beg + j], s1 = g_csrc[beg + j + 1];
        int s2 = g_csrc[beg + j + 2], s3 = g_csrc[beg + j + 3];
        float w0 = g_cnorm[beg + j], w1 = g_cnorm[beg + j + 1];
        float w2 = g_cnorm[beg + j + 2], w3 = g_cnorm[beg + j + 3];
        float4 v0 = hw4[s0 * 32 + lane];
        float4 v1 = hw4[s1 * 32 + lane];
        float4 v2 = hw4[s2 * 32 + lane];
        float4 v3 = hw4[s3 * 32 + lane];
        acc.x += v0.x * w0 + v1.x * w1 + v2.x * w2 + v3.x * w3;
        acc.y += v0.y * w0 + v1.y * w1 + v2.y * w2 + v3.y * w3;
        acc.z += v0.z * w0 + v1.z * w1 + v2.z * w2 + v3.z * w3;
        acc.w += v0.w * w0 + v1.w * w1 + v2.w * w2 + v3.w * w3;
    }
    for (; j < cnt; j++) {
        int s0 = g_csrc[beg + j];
        float w0 = g_cnorm[beg + j];
        float4 v0 = hw4[s0 * 32 + lane];
        acc.x += v0.x * w0;
        acc.y += v0.y * w0;
        acc.z += v0.z * w0;
        acc.w += v0.w * w0;
    }
    st4(&g_agg[n * DD + lane * 4], acc);
}

// ---------------- GEMM: hw = relu(agg) @ W   (M=50000, N=128, K=128) ----------------
#define BM 64
#define BK 16
__global__ void k_gemm(const float* __restrict__ W) {
    __shared__ float As[BK][BM];
    __shared__ float Bs[BK][DD];
    int m0 = blockIdx.x * BM;
    int tid = threadIdx.x;            // 256
    int tx = tid & 31;                // col group: cols tx*4 .. tx*4+3
    int ty = tid >> 5;                // row group: rows ty*8 .. ty*8+7

    float acc[8][4];
    #pragma unroll
    for (int i = 0; i < 8; i++)
        #pragma unroll
        for (int jj = 0; jj < 4; jj++) acc[i][jj] = 0.f;

    int arow = tid >> 2;              // 0..63
    int akg  = (tid & 3) * 4;         // 0,4,8,12

    for (int k0 = 0; k0 < DD; k0 += BK) {
        // A tile (transposed into smem), relu applied at load
        int gr = m0 + arow;
        float4 av = make_float4(0.f, 0.f, 0.f, 0.f);
        if (gr < NN) av = ld4(&g_agg[gr * DD + k0 + akg]);
        av.x = fmaxf(av.x, 0.f); av.y = fmaxf(av.y, 0.f);
        av.z = fmaxf(av.z, 0.f); av.w = fmaxf(av.w, 0.f);
        As[akg + 0][arow] = av.x;
        As[akg + 1][arow] = av.y;
        As[akg + 2][arow] = av.z;
        As[akg + 3][arow] = av.w;
        // B tile
        #pragma unroll
        for (int t = 0; t < 2; t++) {
            int f = tid + t * 256;    // float4 id in [0,512)
            int kk = f >> 5;
            int c4 = f & 31;
            *(float4*)&Bs[kk][c4 * 4] = ld4(&W[(k0 + kk) * DD + c4 * 4]);
        }
        __syncthreads();
        #pragma unroll
        for (int k = 0; k < BK; k++) {
            float4 b4 = *(float4*)&Bs[k][tx * 4];
            float4 a0 = *(float4*)&As[k][ty * 8];
            float4 a1 = *(float4*)&As[k][ty * 8 + 4];
            float a[8] = {a0.x, a0.y, a0.z, a0.w, a1.x, a1.y, a1.z, a1.w};
            #pragma unroll
            for (int i = 0; i < 8; i++) {
                acc[i][0] += a[i] * b4.x;
                acc[i][1] += a[i] * b4.y;
                acc[i][2] += a[i] * b4.z;
                acc[i][3] += a[i] * b4.w;
            }
        }
        __syncthreads();
    }
    #pragma unroll
    for (int i = 0; i < 8; i++) {
        int gr = m0 + ty * 8 + i;
        if (gr < NN) {
            float4 v = make_float4(acc[i][0], acc[i][1], acc[i][2], acc[i][3]);
            st4(&g_hw[gr * DD + tx * 4], v);
        }
    }
}

// ---------------- pooling ----------------
__global__ void k_pool(const int* __restrict__ batch) {
    int idx = blockIdx.x * blockDim.x + threadIdx.x;   // NN*32
    int n = idx >> 5;
    int lane = idx & 31;
    float4 v = ld4(&g_agg[n * DD + lane * 4]);
    v.x = fmaxf(v.x, 0.f); v.y = fmaxf(v.y, 0.f);
    v.z = fmaxf(v.z, 0.f); v.w = fmaxf(v.w, 0.f);
    int g = batch[n];
    float* p = &g_pooled[g * DD + lane * 4];
    atomicAdd(p + 0, v.x);
    atomicAdd(p + 1, v.y);
    atomicAdd(p + 2, v.z);
    atomicAdd(p + 3, v.w);
}

__global__ void k_count(const int* __restrict__ batch) {
    int i = blockIdx.x * blockDim.x + threadIdx.x;
    if (i < NN) atomicAdd(&g_counts[batch[i]], 1.0f);
}

// ---------------- final FC: out = (pooled/cnt) @ fc_w + fc_b ----------------
__global__ void k_fc(const float* __restrict__ fc_w, const float* __restrict__ fc_b,
                     float* __restrict__ out) {
    __shared__ float pm[DD];
    int g = blockIdx.x;               // 512 blocks
    int o = threadIdx.x;              // 64
    float inv = 1.0f / fmaxf(g_counts[g], 1.0f);
    pm[o]      = g_pooled[g * DD + o] * inv;
    pm[o + 64] = g_pooled[g * DD + o + 64] * inv;
    __syncthreads();
    float s = fc_b[o];
    #pragma unroll 8
    for (int k = 0; k < DD; k++) s += pm[k] * fc_w[k * NO + o];
    out[g * NO + o] = s;
}

// ---------------- launch ----------------
extern "C" void kernel_launch(void* const* d_in, const int* in_sizes, int n_in,
                              void* d_out, int out_size) {
    const int*   x     = (const int*)d_in[0];
    const int*   eidx  = (const int*)d_in[1];
    const int*   batch = (const int*)d_in[2];
    const float* embed = (const float*)d_in[3];
    const float* W0    = (const float*)d_in[4];
    const float* b0    = (const float*)d_in[5];
    const float* W1    = (const float*)d_in[6];
    const float* b1    = (const float*)d_in[7];
    const float* W2    = (const float*)d_in[8];
    const float* b2    = (const float*)d_in[9];
    const float* fc_w  = (const float*)d_in[10];
    const float* fc_b  = (const float*)d_in[11];
    float* out = (float*)d_out;

    const int* src = eidx;           // edge_index[0]
    const int* dst = eidx + NE;      // edge_index[1]

    void *p_degi, *p_cursor, *p_pooled, *p_counts;
    cudaGetSymbolAddress(&p_degi, g_degi);
    cudaGetSymbolAddress(&p_cursor, g_cursor);
    cudaGetSymbolAddress(&p_pooled, g_pooled);
    cudaGetSymbolAddress(&p_counts, g_counts);

    cudaMemsetAsync(p_degi,   0, NN * sizeof(int));
    cudaMemsetAsync(p_cursor, 0, NN * sizeof(int));
    cudaMemsetAsync(p_pooled, 0, NG * DD * sizeof(float));
    cudaMemsetAsync(p_counts, 0, NG * sizeof(float));

    // graph structure
    k_deg<<<(NE + 255) / 256, 256>>>(dst);
    k_dinv<<<(NN + 255) / 256, 256>>>();
    k_scan1<<<NCHUNK, SCAN_BLK>>>();
    k_scan2<<<1, 1>>>();
    k_scan3<<<(NN + 255) / 256, 256>>>();
    k_fill<<<(NE + 255) / 256, 256>>>(src, dst);

    // layer 0 (GEMM folded into 11x128 precompute + gather)
    k_t11<<<NT, DD>>>(embed, W0);
    k_init0<<<(NN * 32) / 256, 256>>>(x);
    k_agg<<<NN / 8, 256>>>(b0);

    // layer 1
    k_gemm<<<(NN + BM - 1) / BM, 256>>>(W1);
    k_agg<<<NN / 8, 256>>>(b1);

    // layer 2
    k_gemm<<<(NN + BM - 1) / BM, 256>>>(W2);
    k_agg<<<NN / 8, 256>>>(b2);

    // pool + fc
    k_pool<<<(NN * 32) / 256, 256>>>(batch);
    k_count<<<(NN + 255) / 256, 256>>>(batch);
    k_fc<<<NG, NO>>>(fc_w, fc_b, out);
}

// round 2
// speedup vs baseline: 1.0005x; 1.0005x over previous
#include <cuda_runtime.h>
#include <cuda_bf16.h>

#define NN 50000
#define NE 500000
#define NG 512
#define DD 128
#define NO 64
#define NT 11
#define SCAN_BLK 512
#define NCHUNK ((NN + SCAN_BLK - 1) / SCAN_BLK)   // 98

// ---------------- device scratch (no allocations allowed) ----------------
__device__ float g_dinv[NN];
__device__ int   g_degi[NN];
__device__ int   g_rowstart[NN];
__device__ int   g_cursor[NN];
__device__ int   g_csrc[NE];
__device__ float g_cnorm[NE];
__device__ float g_hw[NN * DD];     // h @ W  (message content)
__device__ float g_agg[NN * DD];    // pre-relu layer output
__device__ float g_t11[NT * DD];    // embed @ W0
__device__ float g_pooled[NG * DD];
__device__ float g_counts[NG];
__device__ int   g_chunksum[NCHUNK];
__device__ int   g_chunkoff[NCHUNK];

// ---------------- small helpers ----------------
__device__ __forceinline__ float4 ld4(const float* p) { return *(const float4*)p; }
__device__ __forceinline__ void st4(float* p, float4 v) { *(float4*)p = v; }

// ---------------- degree count ----------------
__global__ void k_deg(const int* __restrict__ dst) {
    int i = blockIdx.x * blockDim.x + threadIdx.x;
    if (i < NE) atomicAdd(&g_degi[dst[i]], 1);
}

__global__ void k_dinv() {
    int i = blockIdx.x * blockDim.x + threadIdx.x;
    if (i < NN) g_dinv[i] = rsqrtf((float)g_degi[i] + 1.0f);
}

// ---------------- prefix scan (3-phase) ----------------
__global__ void k_scan1() {
    __shared__ int sh[SCAN_BLK];
    int c = blockIdx.x;
    int i = c * SCAN_BLK + threadIdx.x;
    int v = (i < NN) ? g_degi[i] : 0;
    sh[threadIdx.x] = v;
    __syncthreads();
    #pragma unroll
    for (int off = 1; off < SCAN_BLK; off <<= 1) {
        int t = (threadIdx.x >= off) ? sh[threadIdx.x - off] : 0;
        __syncthreads();
        sh[threadIdx.x] += t;
        __syncthreads();
    }
    if (i < NN) g_rowstart[i] = sh[threadIdx.x] - v;   // exclusive
    if (threadIdx.x == SCAN_BLK - 1) g_chunksum[c] = sh[SCAN_BLK - 1];
}

__global__ void k_scan2() {
    int run = 0;
    for (int k = 0; k < NCHUNK; k++) {
        int t = g_chunksum[k];
        g_chunkoff[k] = run;
        run += t;
    }
}

__global__ void k_scan3() {
    int i = blockIdx.x * blockDim.x + threadIdx.x;
    if (i < NN) g_rowstart[i] += g_chunkoff[i / SCAN_BLK];
}

// ---------------- CSR fill ----------------
__global__ void k_fill(const int* __restrict__ src, const int* __restrict__ dst) {
    int e = blockIdx.x * blockDim.x + threadIdx.x;
    if (e >= NE) return;
    int s = src[e], d = dst[e];
    int pos = atomicAdd(&g_cursor[d], 1);
    int idx = g_rowstart[d] + pos;
    g_csrc[idx]  = s;
    g_cnorm[idx] = g_dinv[s] * g_dinv[d];
}

// ---------------- t11 = embed @ W0 (11x128) ----------------
__global__ void k_t11(const float* __restrict__ embed, const float* __restrict__ W0) {
    __shared__ float er[DD];
    int r = blockIdx.x;       // 0..10
    int c = threadIdx.x;      // 0..127
    er[c] = embed[r * DD + c];
    __syncthreads();
    float s = 0.f;
    #pragma unroll 8
    for (int k = 0; k < DD; k++) s += er[k] * W0[k * DD + c];
    g_t11[r * DD + c] = s;
}

// ---------------- layer-0: hw = t11[x[n]] ----------------
__global__ void k_init0(const int* __restrict__ x) {
    int idx = blockIdx.x * blockDim.x + threadIdx.x;   // NN*32 threads
    int n = idx >> 5;
    int lane = idx & 31;
    float4 v = ld4(&g_t11[x[n] * DD + lane * 4]);
    st4(&g_hw[n * DD + lane * 4], v);
}

// ---------------- aggregation: agg[n] = b + hw[n]*dinv^2 + sum_e hw[src]*enorm ----------------
__global__ void k_agg(const float* __restrict__ b) {
    int n = blockIdx.x * 8 + (threadIdx.x >> 5);       // warp per node, 6250 blocks x 8 warps
    int lane = threadIdx.x & 31;
    const float4* hw4 = (const float4*)g_hw;

    float sn = g_dinv[n];
    sn = sn * sn;
    float4 bv = ld4(&b[lane * 4]);
    float4 hv = hw4[n * 32 + lane];
    float4 acc;
    acc.x = bv.x + hv.x * sn;
    acc.y = bv.y + hv.y * sn;
    acc.z = bv.z + hv.z * sn;
    acc.w = bv.w + hv.w * sn;

    int beg = g_rowstart[n];
    int cnt = g_degi[n];
    int j = 0;
    for (; j + 4 <= cnt; j += 4) {
        int s0 = g_csrc[beg + j], s1 = g_csrc[beg + j + 1];
        int s2 = g_csrc[beg + j + 2], s3 = g_csrc[beg + j + 3];
        float w0 = g_cnorm[beg + j], w1 = g_cnorm[beg + j + 1];
        float w2 = g_cnorm[beg + j + 2], w3 = g_cnorm[beg + j + 3];
        float4 v0 = hw4[s0 * 32 + lane];
        float4 v1 = hw4[s1 * 32 + lane];
        float4 v2 = hw4[s2 * 32 + lane];
        float4 v3 = hw4[s3 * 32 + lane];
        acc.x += v0.x * w0 + v1.x * w1 + v2.x * w2 + v3.x * w3;
        acc.y += v0.y * w0 + v1.y * w1 + v2.y * w2 + v3.y * w3;
        acc.z += v0.z * w0 + v1.z * w1 + v2.z * w2 + v3.z * w3;
        acc.w += v0.w * w0 + v1.w * w1 + v2.w * w2 + v3.w * w3;
    }
    for (; j < cnt; j++) {
        int s0 = g_csrc[beg + j];
        float w0 = g_cnorm[beg + j];
        float4 v0 = hw4[s0 * 32 + lane];
        acc.x += v0.x * w0;
        acc.y += v0.y * w0;
        acc.z += v0.z * w0;
        acc.w += v0.w * w0;
    }
    st4(&g_agg[n * DD + lane * 4], acc);
}

// ---------------- GEMM: hw = relu(agg) @ W   (M=50000, N=128, K=128) ----------------
#define BM 64
#define BK 16
__global__ void k_gemm(const float* __restrict__ W) {
    __shared__ float As[BK][BM];
    __shared__ float Bs[BK][DD];
    int m0 = blockIdx.x * BM;
    int tid = threadIdx.x;            // 256
    int tx = tid & 31;                // col group: cols tx*4 .. tx*4+3
    int ty = tid >> 5;                // row group: rows ty*8 .. ty*8+7

    float acc[8][4];
    #pragma unroll
    for (int i = 0; i < 8; i++)
        #pragma unroll
        for (int jj = 0; jj < 4; jj++) acc[i][jj] = 0.f;

    int arow = tid >> 2;              // 0..63
    int akg  = (tid & 3) * 4;         // 0,4,8,12

    for (int k0 = 0; k0 < DD; k0 += BK) {
        // A tile (transposed into smem), relu applied at load
        int gr = m0 + arow;
        float4 av = make_float4(0.f, 0.f, 0.f, 0.f);
        if (gr < NN) av = ld4(&g_agg[gr * DD + k0 + akg]);
        av.x = fmaxf(av.x, 0.f); av.y = fmaxf(av.y, 0.f);
        av.z = fmaxf(av.z, 0.f); av.w = fmaxf(av.w, 0.f);
        As[akg + 0][arow] = av.x;
        As[akg + 1][arow] = av.y;
        As[akg + 2][arow] = av.z;
        As[akg + 3][arow] = av.w;
        // B tile
        #pragma unroll
        for (int t = 0; t < 2; t++) {
            int f = tid + t * 256;    // float4 id in [0,512)
            int kk = f >> 5;
            int c4 = f & 31;
            *(float4*)&Bs[kk][c4 * 4] = ld4(&W[(k0 + kk) * DD + c4 * 4]);
        }
        __syncthreads();
        #pragma unroll
        for (int k = 0; k < BK; k++) {
            float4 b4 = *(float4*)&Bs[k][tx * 4];
            float4 a0 = *(float4*)&As[k][ty * 8];
            float4 a1 = *(float4*)&As[k][ty * 8 + 4];
            float a[8] = {a0.x, a0.y, a0.z, a0.w, a1.x, a1.y, a1.z, a1.w};
            #pragma unroll
            for (int i = 0; i < 8; i++) {
                acc[i][0] += a[i] * b4.x;
                acc[i][1] += a[i] * b4.y;
                acc[i][2] += a[i] * b4.z;
                acc[i][3] += a[i] * b4.w;
            }
        }
        __syncthreads();
    }
    #pragma unroll
    for (int i = 0; i < 8; i++) {
        int gr = m0 + ty * 8 + i;
        if (gr < NN) {
            float4 v = make_float4(acc[i][0], acc[i][1], acc[i][2], acc[i][3]);
            st4(&g_hw[gr * DD + tx * 4], v);
        }
    }
}

// ---------------- pooling ----------------
__global__ void k_pool(const int* __restrict__ batch) {
    int idx = blockIdx.x * blockDim.x + threadIdx.x;   // NN*32
    int n = idx >> 5;
    int lane = idx & 31;
    float4 v = ld4(&g_agg[n * DD + lane * 4]);
    v.x = fmaxf(v.x, 0.f); v.y = fmaxf(v.y, 0.f);
    v.z = fmaxf(v.z, 0.f); v.w = fmaxf(v.w, 0.f);
    int g = batch[n];
    float* p = &g_pooled[g * DD + lane * 4];
    atomicAdd(p + 0, v.x);
    atomicAdd(p + 1, v.y);
    atomicAdd(p + 2, v.z);
    atomicAdd(p + 3, v.w);
}

__global__ void k_count(const int* __restrict__ batch) {
    int i = blockIdx.x * blockDim.x + threadIdx.x;
    if (i < NN) atomicAdd(&g_counts[batch[i]], 1.0f);
}

// ---------------- final FC: out = (pooled/cnt) @ fc_w + fc_b ----------------
__global__ void k_fc(const float* __restrict__ fc_w, const float* __restrict__ fc_b,
                     float* __restrict__ out) {
    __shared__ float pm[DD];
    int g = blockIdx.x;               // 512 blocks
    int o = threadIdx.x;              // 64
    float inv = 1.0f / fmaxf(g_counts[g], 1.0f);
    pm[o]      = g_pooled[g * DD + o] * inv;
    pm[o + 64] = g_pooled[g * DD + o + 64] * inv;
    __syncthreads();
    float s = fc_b[o];
    #pragma unroll 8
    for (int k = 0; k < DD; k++) s += pm[k] * fc_w[k * NO + o];
    out[g * NO + o] = s;
}

// ---------------- launch ----------------
extern "C" void kernel_launch(void* const* d_in, const int* in_sizes, int n_in,
                              void* d_out, int out_size) {
    const int*   x     = (const int*)d_in[0];
    const int*   eidx  = (const int*)d_in[1];
    const int*   batch = (const int*)d_in[2];
    const float* embed = (const float*)d_in[3];
    const float* W0    = (const float*)d_in[4];
    const float* b0    = (const float*)d_in[5];
    const float* W1    = (const float*)d_in[6];
    const float* b1    = (const float*)d_in[7];
    const float* W2    = (const float*)d_in[8];
    const float* b2    = (const float*)d_in[9];
    const float* fc_w  = (const float*)d_in[10];
    const float* fc_b  = (const float*)d_in[11];
    float* out = (float*)d_out;

    const int* src = eidx;           // edge_index[0]
    const int* dst = eidx + NE;      // edge_index[1]

    void *p_degi, *p_cursor, *p_pooled, *p_counts;
    cudaGetSymbolAddress(&p_degi, g_degi);
    cudaGetSymbolAddress(&p_cursor, g_cursor);
    cudaGetSymbolAddress(&p_pooled, g_pooled);
    cudaGetSymbolAddress(&p_counts, g_counts);

    cudaMemsetAsync(p_degi,   0, NN * sizeof(int));
    cudaMemsetAsync(p_cursor, 0, NN * sizeof(int));
    cudaMemsetAsync(p_pooled, 0, NG * DD * sizeof(float));
    cudaMemsetAsync(p_counts, 0, NG * sizeof(float));

    // graph structure
    k_deg<<<(NE + 255) / 256, 256>>>(dst);
    k_dinv<<<(NN + 255) / 256, 256>>>();
    k_scan1<<<NCHUNK, SCAN_BLK>>>();
    k_scan2<<<1, 1>>>();
    k_scan3<<<(NN + 255) / 256, 256>>>();
    k_fill<<<(NE + 255) / 256, 256>>>(src, dst);

    // layer 0 (GEMM folded into 11x128 precompute + gather)
    k_t11<<<NT, DD>>>(embed, W0);
    k_init0<<<(NN * 32) / 256, 256>>>(x);
    k_agg<<<NN / 8, 256>>>(b0);

    // layer 1
    k_gemm<<<(NN + BM - 1) / BM, 256>>>(W1);
    k_agg<<<NN / 8, 256>>>(b1);

    // layer 2
    k_gemm<<<(NN + BM - 1) / BM, 256>>>(W2);
    k_agg<<<NN / 8, 256>>>(b2);

    // pool + fc
    k_pool<<<(NN * 32) / 256, 256>>>(batch);
    k_count<<<(NN + 255) / 256, 256>>>(batch);
    k_fc<<<NG, NO>>>(fc_w, fc_b, out);
}

// round 3
// speedup vs baseline: 1.4478x; 1.4471x over previous
#include <cuda_runtime.h>
#include <cuda_bf16.h>
#include <mma.h>

using namespace nvcuda;

#define NN 50000
#define NNP 50048              // padded to 391*128 for guard-free GEMM
#define NE 500000
#define NG 512
#define DD 128
#define NO 64
#define NT 11
#define SCAN_BLK 512
#define NCHUNK ((NN + SCAN_BLK - 1) / SCAN_BLK)   // 98

// ---------------- device scratch ----------------
__device__ float g_dinv[NN];
__device__ int   g_degi[NN];
__device__ int   g_rowstart[NN];
__device__ int   g_cursor[NN];
__device__ int   g_csrc[NE];
__device__ float g_cnorm[NE];
__device__ float g_hw[NNP * DD];    // h @ W (message content); pad rows stay 0
__device__ float g_agg[NNP * DD];   // pre-relu layer output;   pad rows stay 0
__device__ float g_t11[NT * DD];    // embed @ W0
__device__ int   g_chunksum[NCHUNK];
__device__ int   g_gstart[NG + 1];

__device__ __forceinline__ float4 ld4(const float* p) { return *(const float4*)p; }
__device__ __forceinline__ void st4(float* p, float4 v) { *(float4*)p = v; }

// ---------------- degree count ----------------
__global__ void k_deg(const int* __restrict__ dst) {
    int i = blockIdx.x * blockDim.x + threadIdx.x;
    if (i < NE) atomicAdd(&g_degi[dst[i]], 1);
}

// ---------------- scan phase 1 (+ dinv fused) ----------------
__global__ void k_scan1() {
    __shared__ int sh[SCAN_BLK];
    int c = blockIdx.x;
    int i = c * SCAN_BLK + threadIdx.x;
    int v = (i < NN) ? g_degi[i] : 0;
    if (i < NN) g_dinv[i] = rsqrtf((float)v + 1.0f);
    sh[threadIdx.x] = v;
    __syncthreads();
    #pragma unroll
    for (int off = 1; off < SCAN_BLK; off <<= 1) {
        int t = (threadIdx.x >= off) ? sh[threadIdx.x - off] : 0;
        __syncthreads();
        sh[threadIdx.x] += t;
        __syncthreads();
    }
    if (i < NN) g_rowstart[i] = sh[threadIdx.x] - v;   // exclusive within chunk
    if (threadIdx.x == SCAN_BLK - 1) g_chunksum[c] = sh[SCAN_BLK - 1];
}

// ---------------- scan phase 2: per-block chunk-prefix (no serial kernel) ----------------
__global__ void k_scan3() {
    __shared__ int soff;
    int c = blockIdx.x;
    if (threadIdx.x == 0) {
        int r = 0;
        for (int k = 0; k < c; k++) r += g_chunksum[k];
        soff = r;
    }
    __syncthreads();
    int i = c * SCAN_BLK + threadIdx.x;
    if (i < NN) g_rowstart[i] += soff;
}

// ---------------- CSR fill ----------------
__global__ void k_fill(const int* __restrict__ src, const int* __restrict__ dst) {
    int e = blockIdx.x * blockDim.x + threadIdx.x;
    if (e >= NE) return;
    int s = src[e], d = dst[e];
    int pos = atomicAdd(&g_cursor[d], 1);
    int idx = g_rowstart[d] + pos;
    g_csrc[idx]  = s;
    g_cnorm[idx] = g_dinv[s] * g_dinv[d];
}

// ---------------- t11 = embed @ W0 (11x128) ----------------
__global__ void k_t11(const float* __restrict__ embed, const float* __restrict__ W0) {
    __shared__ float er[DD];
    int r = blockIdx.x;
    int c = threadIdx.x;
    er[c] = embed[r * DD + c];
    __syncthreads();
    float s = 0.f;
    #pragma unroll 8
    for (int k = 0; k < DD; k++) s += er[k] * W0[k * DD + c];
    g_t11[r * DD + c] = s;
}

// ---------------- layer-0 aggregation fused with embedding gather ----------------
__global__ void k_agg0(const float* __restrict__ b, const int* __restrict__ x) {
    __shared__ float st[NT * DD];
    for (int i = threadIdx.x; i < NT * DD; i += 256) st[i] = g_t11[i];
    __syncthreads();

    int n = blockIdx.x * 8 + (threadIdx.x >> 5);
    int lane = threadIdx.x & 31;
    const float4* st4p = (const float4*)st;

    float sn = g_dinv[n]; sn = sn * sn;
    float4 bv = ld4(&b[lane * 4]);
    float4 hv = st4p[x[n] * 32 + lane];
    float4 acc;
    acc.x = bv.x + hv.x * sn;
    acc.y = bv.y + hv.y * sn;
    acc.z = bv.z + hv.z * sn;
    acc.w = bv.w + hv.w * sn;

    int beg = g_rowstart[n];
    int cnt = g_degi[n];
    int j = 0;
    for (; j + 4 <= cnt; j += 4) {
        int s0 = x[g_csrc[beg + j]],     s1 = x[g_csrc[beg + j + 1]];
        int s2 = x[g_csrc[beg + j + 2]], s3 = x[g_csrc[beg + j + 3]];
        float w0 = g_cnorm[beg + j],     w1 = g_cnorm[beg + j + 1];
        float w2 = g_cnorm[beg + j + 2], w3 = g_cnorm[beg + j + 3];
        float4 v0 = st4p[s0 * 32 + lane];
        float4 v1 = st4p[s1 * 32 + lane];
        float4 v2 = st4p[s2 * 32 + lane];
        float4 v3 = st4p[s3 * 32 + lane];
        acc.x += v0.x * w0 + v1.x * w1 + v2.x * w2 + v3.x * w3;
        acc.y += v0.y * w0 + v1.y * w1 + v2.y * w2 + v3.y * w3;
        acc.z += v0.z * w0 + v1.z * w1 + v2.z * w2 + v3.z * w3;
        acc.w += v0.w * w0 + v1.w * w1 + v2.w * w2 + v3.w * w3;
    }
    for (; j < cnt; j++) {
        int s0 = x[g_csrc[beg + j]];
        float w0 = g_cnorm[beg + j];
        float4 v0 = st4p[s0 * 32 + lane];
        acc.x += v0.x * w0; acc.y += v0.y * w0;
        acc.z += v0.z * w0; acc.w += v0.w * w0;
    }
    st4(&g_agg[n * DD + lane * 4], acc);
}

// ---------------- generic aggregation (layers 1,2) ----------------
__global__ void k_agg(const float* __restrict__ b) {
    int n = blockIdx.x * 8 + (threadIdx.x >> 5);
    int lane = threadIdx.x & 31;
    const float4* hw4 = (const float4*)g_hw;

    float sn = g_dinv[n]; sn = sn * sn;
    float4 bv = ld4(&b[lane * 4]);
    float4 hv = hw4[n * 32 + lane];
    float4 acc;
    acc.x = bv.x + hv.x * sn;
    acc.y = bv.y + hv.y * sn;
    acc.z = bv.z + hv.z * sn;
    acc.w = bv.w + hv.w * sn;

    int beg = g_rowstart[n];
    int cnt = g_degi[n];
    int j = 0;
    for (; j + 4 <= cnt; j += 4) {
        int s0 = g_csrc[beg + j],     s1 = g_csrc[beg + j + 1];
        int s2 = g_csrc[beg + j + 2], s3 = g_csrc[beg + j + 3];
        float w0 = g_cnorm[beg + j],     w1 = g_cnorm[beg + j + 1];
        float w2 = g_cnorm[beg + j + 2], w3 = g_cnorm[beg + j + 3];
        float4 v0 = hw4[s0 * 32 + lane];
        float4 v1 = hw4[s1 * 32 + lane];
        float4 v2 = hw4[s2 * 32 + lane];
        float4 v3 = hw4[s3 * 32 + lane];
        acc.x += v0.x * w0 + v1.x * w1 + v2.x * w2 + v3.x * w3;
        acc.y += v0.y * w0 + v1.y * w1 + v2.y * w2 + v3.y * w3;
        acc.z += v0.z * w0 + v1.z * w1 + v2.z * w2 + v3.z * w3;
        acc.w += v0.w * w0 + v1.w * w1 + v2.w * w2 + v3.w * w3;
    }
    for (; j < cnt; j++) {
        int s0 = g_csrc[beg + j];
        float w0 = g_cnorm[beg + j];
        float4 v0 = hw4[s0 * 32 + lane];
        acc.x += v0.x * w0; acc.y += v0.y * w0;
        acc.z += v0.z * w0; acc.w += v0.w * w0;
    }
    st4(&g_agg[n * DD + lane * 4], acc);
}

// ---------------- tf32 tensor-core GEMM: hw = relu(agg) @ W ----------------
// M=50048 (padded), N=128, K=128. Block tile 128x128, 8 warps (4m x 2n),
// each warp 32x64 = 2x4 wmma 16x16x8 tf32 frags.
#define APAD 40     // A smem row stride (floats)
#define BPAD 136    // B smem row stride (floats)
__global__ __launch_bounds__(256) void k_gemm(const float* __restrict__ W) {
    __shared__ float As[128 * APAD];
    __shared__ float Bs[32 * BPAD];
    int m0 = blockIdx.x * 128;
    int tid = threadIdx.x;
    int wid = tid >> 5;
    int warp_m = wid >> 1;        // 0..3
    int warp_n = wid & 1;         // 0..1

    wmma::fragment<wmma::accumulator, 16, 16, 8, float> c[2][4];
    #pragma unroll
    for (int i = 0; i < 2; i++)
        #pragma unroll
        for (int j = 0; j < 4; j++) wmma::fill_fragment(c[i][j], 0.0f);

    for (int k0 = 0; k0 < DD; k0 += 32) {
        // A tile: 128 rows x 32 k, relu + tf32 convert at store
        #pragma unroll
        for (int t = 0; t < 4; t++) {
            int f = tid + t * 256;          // float4 id in [0,1024)
            int row = f >> 3, c4 = (f & 7) * 4;
            float4 v = ld4(&g_agg[(m0 + row) * DD + k0 + c4]);
            float* d = &As[row * APAD + c4];
            d[0] = wmma::__float_to_tf32(fmaxf(v.x, 0.f));
            d[1] = wmma::__float_to_tf32(fmaxf(v.y, 0.f));
            d[2] = wmma::__float_to_tf32(fmaxf(v.z, 0.f));
            d[3] = wmma::__float_to_tf32(fmaxf(v.w, 0.f));
        }
        // B tile: 32 k x 128 n
        #pragma unroll
        for (int t = 0; t < 4; t++) {
            int f = tid + t * 256;
            int row = f >> 5, c4 = (f & 31) * 4;
            float4 v = ld4(&W[(k0 + row) * DD + c4]);
            float* d = &Bs[row * BPAD + c4];
            d[0] = wmma::__float_to_tf32(v.x);
            d[1] = wmma::__float_to_tf32(v.y);
            d[2] = wmma::__float_to_tf32(v.z);
            d[3] = wmma::__float_to_tf32(v.w);
        }
        __syncthreads();
        #pragma unroll
        for (int kk = 0; kk < 4; kk++) {
            wmma::fragment<wmma::matrix_a, 16, 16, 8, wmma::precision::tf32, wmma::row_major> a[2];
            wmma::fragment<wmma::matrix_b, 16, 16, 8, wmma::precision::tf32, wmma::row_major> bfr[4];
            #pragma unroll
            for (int i = 0; i < 2; i++)
                wmma::load_matrix_sync(a[i], &As[(warp_m * 32 + i * 16) * APAD + kk * 8], APAD);
            #pragma unroll
            for (int j = 0; j < 4; j++)
                wmma::load_matrix_sync(bfr[j], &Bs[(kk * 8) * BPAD + warp_n * 64 + j * 16], BPAD);
            #pragma unroll
            for (int i = 0; i < 2; i++)
                #pragma unroll
                for (int j = 0; j < 4; j++)
                    wmma::mma_sync(c[i][j], a[i], bfr[j], c[i][j]);
        }
        __syncthreads();
    }
    #pragma unroll
    for (int i = 0; i < 2; i++)
        #pragma unroll
        for (int j = 0; j < 4; j++)
            wmma::store_matrix_sync(
                &g_hw[(m0 + warp_m * 32 + i * 16) * DD + warp_n * 64 + j * 16],
                c[i][j], DD, wmma::mem_row_major);
}

// ---------------- graph boundaries from sorted batch ----------------
__global__ void k_bound(const int* __restrict__ batch) {
    int i = blockIdx.x * blockDim.x + threadIdx.x;
    if (i >= NN) return;
    int b = batch[i];
    int prev = (i == 0) ? -1 : batch[i - 1];
    for (int g = prev + 1; g <= b; g++) g_gstart[g] = i;
    if (i == NN - 1)
        for (int g = b + 1; g <= NG; g++) g_gstart[g] = NN;
}

// ---------------- fused mean-pool + FC ----------------
__global__ void k_poolfc(const float* __restrict__ fc_w, const float* __restrict__ fc_b,
                         float* __restrict__ out) {
    __shared__ float pm[DD];
    int g = blockIdx.x;               // 512 blocks
    int d = threadIdx.x;              // 128 threads
    int s = g_gstart[g], e = g_gstart[g + 1];
    float acc = 0.f;
    for (int n = s; n < e; n++) acc += fmaxf(g_agg[n * DD + d], 0.f);
    float inv = 1.0f / fmaxf((float)(e - s), 1.0f);
    pm[d] = acc * inv;
    __syncthreads();
    if (d < NO) {
        float sum = fc_b[d];
        #pragma unroll 8
        for (int k = 0; k < DD; k++) sum += pm[k] * fc_w[k * NO + d];
        out[g * NO + d] = sum;
    }
}

// ---------------- launch ----------------
extern "C" void kernel_launch(void* const* d_in, const int* in_sizes, int n_in,
                              void* d_out, int out_size) {
    const int*   x     = (const int*)d_in[0];
    const int*   eidx  = (const int*)d_in[1];
    const int*   batch = (const int*)d_in[2];
    const float* embed = (const float*)d_in[3];
    const float* W0    = (const float*)d_in[4];
    const float* b0    = (const float*)d_in[5];
    const float* W1    = (const float*)d_in[6];
    const float* b1    = (const float*)d_in[7];
    const float* W2    = (const float*)d_in[8];
    const float* b2    = (const float*)d_in[9];
    const float* fc_w  = (const float*)d_in[10];
    const float* fc_b  = (const float*)d_in[11];
    float* out = (float*)d_out;

    const int* src = eidx;
    const int* dst = eidx + NE;

    void *p_degi, *p_cursor;
    cudaGetSymbolAddress(&p_degi, g_degi);
    cudaGetSymbolAddress(&p_cursor, g_cursor);
    cudaMemsetAsync(p_degi,   0, NN * sizeof(int));
    cudaMemsetAsync(p_cursor, 0, NN * sizeof(int));

    // graph structure
    k_deg<<<(NE + 255) / 256, 256>>>(dst);
    k_scan1<<<NCHUNK, SCAN_BLK>>>();
    k_scan3<<<NCHUNK, SCAN_BLK>>>();
    k_fill<<<(NE + 255) / 256, 256>>>(src, dst);
    k_bound<<<(NN + 255) / 256, 256>>>(batch);

    // layer 0: embed-gather fused into aggregation
    k_t11<<<NT, DD>>>(embed, W0);
    k_agg0<<<NN / 8, 256>>>(b0, x);

    // layer 1
    k_gemm<<<NNP / 128, 256>>>(W1);
    k_agg<<<NN / 8, 256>>>(b1);

    // layer 2
    k_gemm<<<NNP / 128, 256>>>(W2);
    k_agg<<<NN / 8, 256>>>(b2);

    // pool + fc
    k_poolfc<<<NG, DD>>>(fc_w, fc_b, out);
}

// round 6
// speedup vs baseline: 1.4891x; 1.0285x over previous
#include <cuda_runtime.h>
#include <cuda_bf16.h>
#include <cuda_fp16.h>
#include <mma.h>

using namespace nvcuda;

#define NN 50000
#define NNP 50048              // padded to 391*128 for guard-free GEMM
#define NE 500000
#define NG 512
#define DD 128
#define NO 64
#define NT 11
#define SCAN_BLK 512
#define NCHUNK ((NN + SCAN_BLK - 1) / SCAN_BLK)   // 98

// ---------------- device scratch ----------------
__device__ float  g_dinv[NN];
__device__ int    g_degi[NN];
__device__ int    g_rowstart[NN];
__device__ int    g_cursor[NN];
__device__ int    g_csrc[NE];
__device__ float  g_cnorm[NE];
__device__ __half g_hw[NNP * DD];    // h @ W in fp16 (message content)
__device__ float  g_agg[NNP * DD];   // pre-relu layer output; pad rows stay 0
__device__ float  g_t11[NT * DD];    // embed @ W0
__device__ int    g_chunksum[NCHUNK];
__device__ int    g_gstart[NG + 1];

__device__ __forceinline__ float4 ld4(const float* p) { return *(const float4*)p; }
__device__ __forceinline__ void st4(float* p, float4 v) { *(float4*)p = v; }

// ---------------- degree count ----------------
__global__ void k_deg(const int* __restrict__ dst) {
    int i = blockIdx.x * blockDim.x + threadIdx.x;
    if (i < NE) atomicAdd(&g_degi[dst[i]], 1);
}

// ---------------- scan phase 1 (+ dinv fused) ----------------
__global__ void k_scan1() {
    __shared__ int sh[SCAN_BLK];
    int c = blockIdx.x;
    int i = c * SCAN_BLK + threadIdx.x;
    int v = (i < NN) ? g_degi[i] : 0;
    if (i < NN) g_dinv[i] = rsqrtf((float)v + 1.0f);
    sh[threadIdx.x] = v;
    __syncthreads();
    #pragma unroll
    for (int off = 1; off < SCAN_BLK; off <<= 1) {
        int t = (threadIdx.x >= off) ? sh[threadIdx.x - off] : 0;
        __syncthreads();
        sh[threadIdx.x] += t;
        __syncthreads();
    }
    if (i < NN) g_rowstart[i] = sh[threadIdx.x] - v;   // exclusive within chunk
    if (threadIdx.x == SCAN_BLK - 1) g_chunksum[c] = sh[SCAN_BLK - 1];
}

// ---------------- scan phase 2: per-block chunk-prefix ----------------
__global__ void k_scan3() {
    __shared__ int soff;
    int c = blockIdx.x;
    if (threadIdx.x == 0) {
        int r = 0;
        for (int k = 0; k < c; k++) r += g_chunksum[k];
        soff = r;
    }
    __syncthreads();
    int i = c * SCAN_BLK + threadIdx.x;
    if (i < NN) g_rowstart[i] += soff;
}

// ---------------- CSR fill ----------------
__global__ void k_fill(const int* __restrict__ src, const int* __restrict__ dst) {
    int e = blockIdx.x * blockDim.x + threadIdx.x;
    if (e >= NE) return;
    int s = src[e], d = dst[e];
    int pos = atomicAdd(&g_cursor[d], 1);
    int idx = g_rowstart[d] + pos;
    g_csrc[idx]  = s;
    g_cnorm[idx] = g_dinv[s] * g_dinv[d];
}

// ---------------- t11 = embed @ W0 (11x128) ----------------
__global__ void k_t11(const float* __restrict__ embed, const float* __restrict__ W0) {
    __shared__ float er[DD];
    int r = blockIdx.x;
    int c = threadIdx.x;
    er[c] = embed[r * DD + c];
    __syncthreads();
    float s = 0.f;
    #pragma unroll 8
    for (int k = 0; k < DD; k++) s += er[k] * W0[k * DD + c];
    g_t11[r * DD + c] = s;
}

// ---------------- layer-0 aggregation fused with embedding gather (fp32 smem table) ----------------
__global__ void k_agg0(const float* __restrict__ b, const int* __restrict__ x) {
    __shared__ float st[NT * DD];
    for (int i = threadIdx.x; i < NT * DD; i += 256) st[i] = g_t11[i];
    __syncthreads();

    int n = blockIdx.x * 8 + (threadIdx.x >> 5);
    int lane = threadIdx.x & 31;
    const float4* st4p = (const float4*)st;

    float sn = g_dinv[n]; sn = sn * sn;
    float4 bv = ld4(&b[lane * 4]);
    float4 hv = st4p[x[n] * 32 + lane];
    float4 acc;
    acc.x = bv.x + hv.x * sn;
    acc.y = bv.y + hv.y * sn;
    acc.z = bv.z + hv.z * sn;
    acc.w = bv.w + hv.w * sn;

    int beg = g_rowstart[n];
    int cnt = g_degi[n];
    int j = 0;
    for (; j + 4 <= cnt; j += 4) {
        int s0 = x[g_csrc[beg + j]],     s1 = x[g_csrc[beg + j + 1]];
        int s2 = x[g_csrc[beg + j + 2]], s3 = x[g_csrc[beg + j + 3]];
        float w0 = g_cnorm[beg + j],     w1 = g_cnorm[beg + j + 1];
        float w2 = g_cnorm[beg + j + 2], w3 = g_cnorm[beg + j + 3];
        float4 v0 = st4p[s0 * 32 + lane];
        float4 v1 = st4p[s1 * 32 + lane];
        float4 v2 = st4p[s2 * 32 + lane];
        float4 v3 = st4p[s3 * 32 + lane];
        acc.x += v0.x * w0 + v1.x * w1 + v2.x * w2 + v3.x * w3;
        acc.y += v0.y * w0 + v1.y * w1 + v2.y * w2 + v3.y * w3;
        acc.z += v0.z * w0 + v1.z * w1 + v2.z * w2 + v3.z * w3;
        acc.w += v0.w * w0 + v1.w * w1 + v2.w * w2 + v3.w * w3;
    }
    for (; j < cnt; j++) {
        int s0 = x[g_csrc[beg + j]];
        float w0 = g_cnorm[beg + j];
        float4 v0 = st4p[s0 * 32 + lane];
        acc.x += v0.x * w0; acc.y += v0.y * w0;
        acc.z += v0.z * w0; acc.w += v0.w * w0;
    }
    st4(&g_agg[n * DD + lane * 4], acc);
}

// ---------------- generic aggregation over fp16 messages (layers 1,2) ----------------
__device__ __forceinline__ void h4acc(uint2 h, float w, float4& acc) {
    float2 f01 = __half22float2(*(__half2*)&h.x);
    float2 f23 = __half22float2(*(__half2*)&h.y);
    acc.x += f01.x * w; acc.y += f01.y * w;
    acc.z += f23.x * w; acc.w += f23.y * w;
}

__global__ void k_agg(const float* __restrict__ b) {
    int n = blockIdx.x * 8 + (threadIdx.x >> 5);
    int lane = threadIdx.x & 31;
    const uint2* hw8 = (const uint2*)g_hw;    // 4 halves per uint2; row = 32 uint2

    float sn = g_dinv[n]; sn = sn * sn;
    float4 bv = ld4(&b[lane * 4]);
    uint2 hs = hw8[n * 32 + lane];
    float2 s01 = __half22float2(*(__half2*)&hs.x);
    float2 s23 = __half22float2(*(__half2*)&hs.y);
    float4 acc;
    acc.x = bv.x + s01.x * sn;
    acc.y = bv.y + s01.y * sn;
    acc.z = bv.z + s23.x * sn;
    acc.w = bv.w + s23.y * sn;

    int beg = g_rowstart[n];
    int cnt = g_degi[n];
    int j = 0;
    for (; j + 4 <= cnt; j += 4) {
        int s0 = g_csrc[beg + j],     s1 = g_csrc[beg + j + 1];
        int s2 = g_csrc[beg + j + 2], s3 = g_csrc[beg + j + 3];
        float w0 = g_cnorm[beg + j],     w1 = g_cnorm[beg + j + 1];
        float w2 = g_cnorm[beg + j + 2], w3 = g_cnorm[beg + j + 3];
        uint2 v0 = hw8[s0 * 32 + lane];
        uint2 v1 = hw8[s1 * 32 + lane];
        uint2 v2 = hw8[s2 * 32 + lane];
        uint2 v3 = hw8[s3 * 32 + lane];
        h4acc(v0, w0, acc); h4acc(v1, w1, acc);
        h4acc(v2, w2, acc); h4acc(v3, w3, acc);
    }
    for (; j < cnt; j++) {
        int s0 = g_csrc[beg + j];
        float w0 = g_cnorm[beg + j];
        h4acc(hw8[s0 * 32 + lane], w0, acc);
    }
    st4(&g_agg[n * DD + lane * 4], acc);
}

// ---------------- tf32 tensor-core GEMM: hw = fp16( relu(agg) @ W ) ----------------
// M=50048, N=128, K=128. Block tile 128x128, 8 warps (4m x 2n),
// warp tile 32x64 = 2x4 wmma 16x16x8 tf32 frags. Epilogue converts to fp16
// via per-warp smem staging (reusing As).
#define APAD 40     // A smem row stride (floats)
#define BPAD 136    // B smem row stride (floats)
__global__ __launch_bounds__(256) void k_gemm(const float* __restrict__ W) {
    __shared__ float As[128 * APAD];
    __shared__ float Bs[32 * BPAD];
    int m0 = blockIdx.x * 128;
    int tid = threadIdx.x;
    int wid = tid >> 5;
    int lane = tid & 31;
    int warp_m = wid >> 1;        // 0..3
    int warp_n = wid & 1;         // 0..1

    wmma::fragment<wmma::accumulator, 16, 16, 8, float> c[2][4];
    #pragma unroll
    for (int i = 0; i < 2; i++)
        #pragma unroll
        for (int j = 0; j < 4; j++) wmma::fill_fragment(c[i][j], 0.0f);

    for (int k0 = 0; k0 < DD; k0 += 32) {
        #pragma unroll
        for (int t = 0; t < 4; t++) {
            int f = tid + t * 256;
            int row = f >> 3, c4 = (f & 7) * 4;
            float4 v = ld4(&g_agg[(m0 + row) * DD + k0 + c4]);
            float* d = &As[row * APAD + c4];
            d[0] = wmma::__float_to_tf32(fmaxf(v.x, 0.f));
            d[1] = wmma::__float_to_tf32(fmaxf(v.y, 0.f));
            d[2] = wmma::__float_to_tf32(fmaxf(v.z, 0.f));
            d[3] = wmma::__float_to_tf32(fmaxf(v.w, 0.f));
        }
        #pragma unroll
        for (int t = 0; t < 4; t++) {
            int f = tid + t * 256;
            int row = f >> 5, c4 = (f & 31) * 4;
            float4 v = ld4(&W[(k0 + row) * DD + c4]);
            float* d = &Bs[row * BPAD + c4];
            d[0] = wmma::__float_to_tf32(v.x);
            d[1] = wmma::__float_to_tf32(v.y);
            d[2] = wmma::__float_to_tf32(v.z);
            d[3] = wmma::__float_to_tf32(v.w);
        }
        __syncthreads();
        #pragma unroll
        for (int kk = 0; kk < 4; kk++) {
            wmma::fragment<wmma::matrix_a, 16, 16, 8, wmma::precision::tf32, wmma::row_major> a[2];
            wmma::fragment<wmma::matrix_b, 16, 16, 8, wmma::precision::tf32, wmma::row_major> bfr[4];
            #pragma unroll
            for (int i = 0; i < 2; i++)
                wmma::load_matrix_sync(a[i], &As[(warp_m * 32 + i * 16) * APAD + kk * 8], APAD);
            #pragma unroll
            for (int j = 0; j < 4; j++)
                wmma::load_matrix_sync(bfr[j], &Bs[(kk * 8) * BPAD + warp_n * 64 + j * 16], BPAD);
            #pragma unroll
            for (int i = 0; i < 2; i++)
                #pragma unroll
                for (int j = 0; j < 4; j++)
                    wmma::mma_sync(c[i][j], a[i], bfr[j], c[i][j]);
        }
        __syncthreads();
    }

    // epilogue: stage each 16x16 frag in smem (reuse As), convert to fp16, 16B stores
    float* stg = &As[wid * 272];            // 272 floats per warp, 16B aligned
    int srow = lane >> 1;
    int scol = (lane & 1) * 8;
    #pragma unroll
    for (int i = 0; i < 2; i++) {
        #pragma unroll
        for (int j = 0; j < 4; j++) {
            wmma::store_matrix_sync(stg, c[i][j], 16, wmma::mem_row_major);
            __syncwarp();
            float4 f0 = *(float4*)&stg[srow * 16 + scol];
            float4 f1 = *(float4*)&stg[srow * 16 + scol + 4];
            __half2 p0 = __floats2half2_rn(f0.x, f0.y);
            __half2 p1 = __floats2half2_rn(f0.z, f0.w);
            __half2 p2 = __floats2half2_rn(f1.x, f1.y);
            __half2 p3 = __floats2half2_rn(f1.z, f1.w);
            uint4 pk = make_uint4(*(unsigned*)&p0, *(unsigned*)&p1,
                                  *(unsigned*)&p2, *(unsigned*)&p3);
            int off = (m0 + warp_m * 32 + i * 16 + srow) * DD + warp_n * 64 + j * 16 + scol;
            *(uint4*)&g_hw[off] = pk;
            __syncwarp();
        }
    }
}

// ---------------- graph boundaries from sorted batch ----------------
__global__ void k_bound(const int* __restrict__ batch) {
    int i = blockIdx.x * blockDim.x + threadIdx.x;
    if (i >= NN) return;
    int b = batch[i];
    int prev = (i == 0) ? -1 : batch[i - 1];
    for (int g = prev + 1; g <= b; g++) g_gstart[g] = i;
    if (i == NN - 1)
        for (int g = b + 1; g <= NG; g++) g_gstart[g] = NN;
}

// ---------------- fused mean-pool + FC ----------------
__global__ void k_poolfc(const float* __restrict__ fc_w, const float* __restrict__ fc_b,
                         float* __restrict__ out) {
    __shared__ float pm[DD];
    int g = blockIdx.x;
    int d = threadIdx.x;
    int s = g_gstart[g], e = g_gstart[g + 1];
    float acc = 0.f;
    for (int n = s; n < e; n++) acc += fmaxf(g_agg[n * DD + d], 0.f);
    float inv = 1.0f / fmaxf((float)(e - s), 1.0f);
    pm[d] = acc * inv;
    __syncthreads();
    if (d < NO) {
        float sum = fc_b[d];
        #pragma unroll 8
        for (int k = 0; k < DD; k++) sum += pm[k] * fc_w[k * NO + d];
        out[g * NO + d] = sum;
    }
}

// ---------------- launch ----------------
extern "C" void kernel_launch(void* const* d_in, const int* in_sizes, int n_in,
                              void* d_out, int out_size) {
    const int*   x     = (const int*)d_in[0];
    const int*   eidx  = (const int*)d_in[1];
    const int*   batch = (const int*)d_in[2];
    const float* embed = (const float*)d_in[3];
    const float* W0    = (const float*)d_in[4];
    const float* b0    = (const float*)d_in[5];
    const float* W1    = (const float*)d_in[6];
    const float* b1    = (const float*)d_in[7];
    const float* W2    = (const float*)d_in[8];
    const float* b2    = (const float*)d_in[9];
    const float* fc_w  = (const float*)d_in[10];
    const float* fc_b  = (const float*)d_in[11];
    float* out = (float*)d_out;

    const int* src = eidx;
    const int* dst = eidx + NE;

    void *p_degi, *p_cursor;
    cudaGetSymbolAddress(&p_degi, g_degi);
    cudaGetSymbolAddress(&p_cursor, g_cursor);
    cudaMemsetAsync(p_degi,   0, NN * sizeof(int));
    cudaMemsetAsync(p_cursor, 0, NN * sizeof(int));

    // graph structure
    k_deg<<<(NE + 255) / 256, 256>>>(dst);
    k_scan1<<<NCHUNK, SCAN_BLK>>>();
    k_scan3<<<NCHUNK, SCAN_BLK>>>();
    k_fill<<<(NE + 255) / 256, 256>>>(src, dst);
    k_bound<<<(NN + 255) / 256, 256>>>(batch);

    // layer 0: embed-gather fused into aggregation
    k_t11<<<NT, DD>>>(embed, W0);
    k_agg0<<<NN / 8, 256>>>(b0, x);

    // layer 1
    k_gemm<<<NNP / 128, 256>>>(W1);
    k_agg<<<NN / 8, 256>>>(b1);

    // layer 2
    k_gemm<<<NNP / 128, 256>>>(W2);
    k_agg<<<NN / 8, 256>>>(b2);

    // pool + fc
    k_poolfc<<<NG, DD>>>(fc_w, fc_b, out);
}

// round 7
// speedup vs baseline: 1.5039x; 1.0099x over previous
#include <cuda_runtime.h>
#include <cuda_bf16.h>
#include <cuda_fp16.h>
#include <mma.h>

using namespace nvcuda;

#define NN 50000
#define NNP 50048              // padded to 391*128 for guard-free GEMM
#define NE 500000
#define NG 512
#define DD 128
#define NO 64
#define NT 11
#define SCAN_BLK 512
#define NCHUNK ((NN + SCAN_BLK - 1) / SCAN_BLK)   // 98

// ---------------- device scratch ----------------
__device__ float  g_dinv[NN];
__device__ int    g_degi[NN];
__device__ int    g_rowstart[NN];
__device__ int    g_cursor[NN];
__device__ int    g_csrc[NE];
__device__ float  g_cnorm[NE];
__device__ __half g_hw[NNP * DD];    // h @ W in fp16 (message content)
__device__ float  g_agg[NNP * DD];   // pre-relu layer output; pad rows stay 0
__device__ float  g_t11[NT * DD];    // embed @ W0
__device__ int    g_chunksum[NCHUNK];
__device__ int    g_gstart[NG + 1];

__device__ __forceinline__ float4 ld4(const float* p) { return *(const float4*)p; }
__device__ __forceinline__ void st4(float* p, float4 v) { *(float4*)p = v; }

// ---------------- degree count ----------------
__global__ void k_deg(const int* __restrict__ dst) {
    int i = blockIdx.x * blockDim.x + threadIdx.x;
    if (i < NE) atomicAdd(&g_degi[dst[i]], 1);
}

// ---------------- scan phase 1 (+ dinv fused) ----------------
__global__ void k_scan1() {
    __shared__ int sh[SCAN_BLK];
    int c = blockIdx.x;
    int i = c * SCAN_BLK + threadIdx.x;
    int v = (i < NN) ? g_degi[i] : 0;
    if (i < NN) g_dinv[i] = rsqrtf((float)v + 1.0f);
    sh[threadIdx.x] = v;
    __syncthreads();
    #pragma unroll
    for (int off = 1; off < SCAN_BLK; off <<= 1) {
        int t = (threadIdx.x >= off) ? sh[threadIdx.x - off] : 0;
        __syncthreads();
        sh[threadIdx.x] += t;
        __syncthreads();
    }
    if (i < NN) g_rowstart[i] = sh[threadIdx.x] - v;   // exclusive within chunk
    if (threadIdx.x == SCAN_BLK - 1) g_chunksum[c] = sh[SCAN_BLK - 1];
}

// ---------------- scan phase 2: per-block chunk-prefix ----------------
__global__ void k_scan3() {
    __shared__ int soff;
    int c = blockIdx.x;
    if (threadIdx.x == 0) {
        int r = 0;
        for (int k = 0; k < c; k++) r += g_chunksum[k];
        soff = r;
    }
    __syncthreads();
    int i = c * SCAN_BLK + threadIdx.x;
    if (i < NN) g_rowstart[i] += soff;
}

// ---------------- CSR fill ----------------
__global__ void k_fill(const int* __restrict__ src, const int* __restrict__ dst) {
    int e = blockIdx.x * blockDim.x + threadIdx.x;
    if (e >= NE) return;
    int s = src[e], d = dst[e];
    int pos = atomicAdd(&g_cursor[d], 1);
    int idx = g_rowstart[d] + pos;
    g_csrc[idx]  = s;
    g_cnorm[idx] = g_dinv[s] * g_dinv[d];
}

// ---------------- t11 = embed @ W0 (11x128) ----------------
__global__ void k_t11(const float* __restrict__ embed, const float* __restrict__ W0) {
    __shared__ float er[DD];
    int r = blockIdx.x;
    int c = threadIdx.x;
    er[c] = embed[r * DD + c];
    __syncthreads();
    float s = 0.f;
    #pragma unroll 8
    for (int k = 0; k < DD; k++) s += er[k] * W0[k * DD + c];
    g_t11[r * DD + c] = s;
}

// ---------------- layer-0 aggregation fused with embedding gather (fp32 smem table) ----------------
__global__ void k_agg0(const float* __restrict__ b, const int* __restrict__ x) {
    __shared__ float st[NT * DD];
    for (int i = threadIdx.x; i < NT * DD; i += 256) st[i] = g_t11[i];
    __syncthreads();

    int n = blockIdx.x * 8 + (threadIdx.x >> 5);
    int lane = threadIdx.x & 31;
    const float4* st4p = (const float4*)st;

    float sn = g_dinv[n]; sn = sn * sn;
    float4 bv = ld4(&b[lane * 4]);
    float4 hv = st4p[x[n] * 32 + lane];
    float4 acc;
    acc.x = bv.x + hv.x * sn;
    acc.y = bv.y + hv.y * sn;
    acc.z = bv.z + hv.z * sn;
    acc.w = bv.w + hv.w * sn;

    int beg = g_rowstart[n];
    int cnt = g_degi[n];
    int j = 0;
    for (; j + 4 <= cnt; j += 4) {
        int s0 = x[g_csrc[beg + j]],     s1 = x[g_csrc[beg + j + 1]];
        int s2 = x[g_csrc[beg + j + 2]], s3 = x[g_csrc[beg + j + 3]];
        float w0 = g_cnorm[beg + j],     w1 = g_cnorm[beg + j + 1];
        float w2 = g_cnorm[beg + j + 2], w3 = g_cnorm[beg + j + 3];
        float4 v0 = st4p[s0 * 32 + lane];
        float4 v1 = st4p[s1 * 32 + lane];
        float4 v2 = st4p[s2 * 32 + lane];
        float4 v3 = st4p[s3 * 32 + lane];
        acc.x += v0.x * w0 + v1.x * w1 + v2.x * w2 + v3.x * w3;
        acc.y += v0.y * w0 + v1.y * w1 + v2.y * w2 + v3.y * w3;
        acc.z += v0.z * w0 + v1.z * w1 + v2.z * w2 + v3.z * w3;
        acc.w += v0.w * w0 + v1.w * w1 + v2.w * w2 + v3.w * w3;
    }
    for (; j < cnt; j++) {
        int s0 = x[g_csrc[beg + j]];
        float w0 = g_cnorm[beg + j];
        float4 v0 = st4p[s0 * 32 + lane];
        acc.x += v0.x * w0; acc.y += v0.y * w0;
        acc.z += v0.z * w0; acc.w += v0.w * w0;
    }
    st4(&g_agg[n * DD + lane * 4], acc);
}

// ---------------- generic aggregation over fp16 messages (layers 1,2) ----------------
__device__ __forceinline__ void h4acc(uint2 h, float w, float4& acc) {
    float2 f01 = __half22float2(*(__half2*)&h.x);
    float2 f23 = __half22float2(*(__half2*)&h.y);
    acc.x += f01.x * w; acc.y += f01.y * w;
    acc.z += f23.x * w; acc.w += f23.y * w;
}

__global__ void k_agg(const float* __restrict__ b) {
    int n = blockIdx.x * 8 + (threadIdx.x >> 5);
    int lane = threadIdx.x & 31;
    const uint2* hw8 = (const uint2*)g_hw;    // 4 halves per uint2; row = 32 uint2

    float sn = g_dinv[n]; sn = sn * sn;
    float4 bv = ld4(&b[lane * 4]);
    uint2 hs = hw8[n * 32 + lane];
    float2 s01 = __half22float2(*(__half2*)&hs.x);
    float2 s23 = __half22float2(*(__half2*)&hs.y);
    float4 acc;
    acc.x = bv.x + s01.x * sn;
    acc.y = bv.y + s01.y * sn;
    acc.z = bv.z + s23.x * sn;
    acc.w = bv.w + s23.y * sn;

    int beg = g_rowstart[n];
    int cnt = g_degi[n];
    int j = 0;
    for (; j + 4 <= cnt; j += 4) {
        int s0 = g_csrc[beg + j],     s1 = g_csrc[beg + j + 1];
        int s2 = g_csrc[beg + j + 2], s3 = g_csrc[beg + j + 3];
        float w0 = g_cnorm[beg + j],     w1 = g_cnorm[beg + j + 1];
        float w2 = g_cnorm[beg + j + 2], w3 = g_cnorm[beg + j + 3];
        uint2 v0 = hw8[s0 * 32 + lane];
        uint2 v1 = hw8[s1 * 32 + lane];
        uint2 v2 = hw8[s2 * 32 + lane];
        uint2 v3 = hw8[s3 * 32 + lane];
        h4acc(v0, w0, acc); h4acc(v1, w1, acc);
        h4acc(v2, w2, acc); h4acc(v3, w3, acc);
    }
    for (; j < cnt; j++) {
        int s0 = g_csrc[beg + j];
        float w0 = g_cnorm[beg + j];
        h4acc(hw8[s0 * 32 + lane], w0, acc);
    }
    st4(&g_agg[n * DD + lane * 4], acc);
}

// ---------------- tf32 tensor-core GEMM: hw = fp16( relu(agg) @ W ) ----------------
// M=50048, N=128, K=128. Block tile 128x128, 8 warps (4m x 2n),
// warp tile 32x64 = 2x4 wmma 16x16x8 tf32 frags. Epilogue converts to fp16
// via per-warp smem staging (reusing As).
#define APAD 40     // A smem row stride (floats)
#define BPAD 136    // B smem row stride (floats)
__global__ __launch_bounds__(256) void k_gemm(const float* __restrict__ W) {
    __shared__ float As[128 * APAD];
    __shared__ float Bs[32 * BPAD];
    int m0 = blockIdx.x * 128;
    int tid = threadIdx.x;
    int wid = tid >> 5;
    int lane = tid & 31;
    int warp_m = wid >> 1;        // 0..3
    int warp_n = wid & 1;         // 0..1

    wmma::fragment<wmma::accumulator, 16, 16, 8, float> c[2][4];
    #pragma unroll
    for (int i = 0; i < 2; i++)
        #pragma unroll
        for (int j = 0; j < 4; j++) wmma::fill_fragment(c[i][j], 0.0f);

    for (int k0 = 0; k0 < DD; k0 += 32) {
        #pragma unroll
        for (int t = 0; t < 4; t++) {
            int f = tid + t * 256;
            int row = f >> 3, c4 = (f & 7) * 4;
            float4 v = ld4(&g_agg[(m0 + row) * DD + k0 + c4]);
            float* d = &As[row * APAD + c4];
            d[0] = wmma::__float_to_tf32(fmaxf(v.x, 0.f));
            d[1] = wmma::__float_to_tf32(fmaxf(v.y, 0.f));
            d[2] = wmma::__float_to_tf32(fmaxf(v.z, 0.f));
            d[3] = wmma::__float_to_tf32(fmaxf(v.w, 0.f));
        }
        #pragma unroll
        for (int t = 0; t < 4; t++) {
            int f = tid + t * 256;
            int row = f >> 5, c4 = (f & 31) * 4;
            float4 v = ld4(&W[(k0 + row) * DD + c4]);
            float* d = &Bs[row * BPAD + c4];
            d[0] = wmma::__float_to_tf32(v.x);
            d[1] = wmma::__float_to_tf32(v.y);
            d[2] = wmma::__float_to_tf32(v.z);
            d[3] = wmma::__float_to_tf32(v.w);
        }
        __syncthreads();
        #pragma unroll
        for (int kk = 0; kk < 4; kk++) {
            wmma::fragment<wmma::matrix_a, 16, 16, 8, wmma::precision::tf32, wmma::row_major> a[2];
            wmma::fragment<wmma::matrix_b, 16, 16, 8, wmma::precision::tf32, wmma::row_major> bfr[4];
            #pragma unroll
            for (int i = 0; i < 2; i++)
                wmma::load_matrix_sync(a[i], &As[(warp_m * 32 + i * 16) * APAD + kk * 8], APAD);
            #pragma unroll
            for (int j = 0; j < 4; j++)
                wmma::load_matrix_sync(bfr[j], &Bs[(kk * 8) * BPAD + warp_n * 64 + j * 16], BPAD);
            #pragma unroll
            for (int i = 0; i < 2; i++)
                #pragma unroll
                for (int j = 0; j < 4; j++)
                    wmma::mma_sync(c[i][j], a[i], bfr[j], c[i][j]);
        }
        __syncthreads();
    }

    // epilogue: stage each 16x16 frag in smem (reuse As), convert to fp16, 16B stores
    float* stg = &As[wid * 272];            // 272 floats per warp, 16B aligned
    int srow = lane >> 1;
    int scol = (lane & 1) * 8;
    #pragma unroll
    for (int i = 0; i < 2; i++) {
        #pragma unroll
        for (int j = 0; j < 4; j++) {
            wmma::store_matrix_sync(stg, c[i][j], 16, wmma::mem_row_major);
            __syncwarp();
            float4 f0 = *(float4*)&stg[srow * 16 + scol];
            float4 f1 = *(float4*)&stg[srow * 16 + scol + 4];
            __half2 p0 = __floats2half2_rn(f0.x, f0.y);
            __half2 p1 = __floats2half2_rn(f0.z, f0.w);
            __half2 p2 = __floats2half2_rn(f1.x, f1.y);
            __half2 p3 = __floats2half2_rn(f1.z, f1.w);
            uint4 pk = make_uint4(*(unsigned*)&p0, *(unsigned*)&p1,
                                  *(unsigned*)&p2, *(unsigned*)&p3);
            int off = (m0 + warp_m * 32 + i * 16 + srow) * DD + warp_n * 64 + j * 16 + scol;
            *(uint4*)&g_hw[off] = pk;
            __syncwarp();
        }
    }
}

// ---------------- graph boundaries from sorted batch ----------------
__global__ void k_bound(const int* __restrict__ batch) {
    int i = blockIdx.x * blockDim.x + threadIdx.x;
    if (i >= NN) return;
    int b = batch[i];
    int prev = (i == 0) ? -1 : batch[i - 1];
    for (int g = prev + 1; g <= b; g++) g_gstart[g] = i;
    if (i == NN - 1)
        for (int g = b + 1; g <= NG; g++) g_gstart[g] = NN;
}

// ---------------- fused mean-pool + FC ----------------
__global__ void k_poolfc(const float* __restrict__ fc_w, const float* __restrict__ fc_b,
                         float* __restrict__ out) {
    __shared__ float pm[DD];
    int g = blockIdx.x;
    int d = threadIdx.x;
    int s = g_gstart[g], e = g_gstart[g + 1];
    float acc = 0.f;
    for (int n = s; n < e; n++) acc += fmaxf(g_agg[n * DD + d], 0.f);
    float inv = 1.0f / fmaxf((float)(e - s), 1.0f);
    pm[d] = acc * inv;
    __syncthreads();
    if (d < NO) {
        float sum = fc_b[d];
        #pragma unroll 8
        for (int k = 0; k < DD; k++) sum += pm[k] * fc_w[k * NO + d];
        out[g * NO + d] = sum;
    }
}

// ---------------- launch ----------------
extern "C" void kernel_launch(void* const* d_in, const int* in_sizes, int n_in,
                              void* d_out, int out_size) {
    const int*   x     = (const int*)d_in[0];
    const int*   eidx  = (const int*)d_in[1];
    const int*   batch = (const int*)d_in[2];
    const float* embed = (const float*)d_in[3];
    const float* W0    = (const float*)d_in[4];
    const float* b0    = (const float*)d_in[5];
    const float* W1    = (const float*)d_in[6];
    const float* b1    = (const float*)d_in[7];
    const float* W2    = (const float*)d_in[8];
    const float* b2    = (const float*)d_in[9];
    const float* fc_w  = (const float*)d_in[10];
    const float* fc_b  = (const float*)d_in[11];
    float* out = (float*)d_out;

    const int* src = eidx;
    const int* dst = eidx + NE;

    void *p_degi, *p_cursor;
    cudaGetSymbolAddress(&p_degi, g_degi);
    cudaGetSymbolAddress(&p_cursor, g_cursor);
    cudaMemsetAsync(p_degi,   0, NN * sizeof(int));
    cudaMemsetAsync(p_cursor, 0, NN * sizeof(int));

    // graph structure
    k_deg<<<(NE + 255) / 256, 256>>>(dst);
    k_scan1<<<NCHUNK, SCAN_BLK>>>();
    k_scan3<<<NCHUNK, SCAN_BLK>>>();
    k_fill<<<(NE + 255) / 256, 256>>>(src, dst);
    k_bound<<<(NN + 255) / 256, 256>>>(batch);

    // layer 0: embed-gather fused into aggregation
    k_t11<<<NT, DD>>>(embed, W0);
    k_agg0<<<NN / 8, 256>>>(b0, x);

    // layer 1
    k_gemm<<<NNP / 128, 256>>>(W1);
    k_agg<<<NN / 8, 256>>>(b1);

    // layer 2
    k_gemm<<<NNP / 128, 256>>>(W2);
    k_agg<<<NN / 8, 256>>>(b2);

    // pool + fc
    k_poolfc<<<NG, DD>>>(fc_w, fc_b, out);
}